// round 7
// baseline (speedup 1.0000x reference)
#include <cuda_runtime.h>
#include <math.h>

// z[b] = sum_t x[b,t]*K[t] + z0 + e
// K[t] = sum_h w_h*b_h*a_h^(T-1-t),  z0 = sum_h w_h*c_h*(1-a_h^T)/(1-a_h)
#define TLEN 4096
#define HDIM 512
#define BATCH 64
#define CHUNK 16
#define SUBS 4                       // sub-chunks per block
#define NBLK (TLEN / (CHUNK * SUBS)) // 64 blocks
#define DSEG 4                       // dot segments per row

// Scratch (__device__ globals; no allocations allowed)
__device__ __align__(16) float g_K[TLEN];

// Kernel 1: 64 blocks x 512 threads. Block j0 covers exponents [64*j0, 64*j0+64)
// as 4 sub-chunks of 16; the geometric chain p *= a runs straight through.
// Block 0 also computes z0 and initializes out[row] = z0 + e (pre-PDL-trigger).
__global__ __launch_bounds__(HDIM) void build_K_kernel(
    const float* __restrict__ a, const float* __restrict__ b,
    const float* __restrict__ c, const float* __restrict__ w,
    const float* __restrict__ e, float* __restrict__ out)
{
    __shared__ float part[CHUNK][HDIM];   // 32 KB
    __shared__ float zp[16];
    __shared__ float s_z0;
    const int h  = threadIdx.x;
    const int j0 = blockIdx.x;
    const int warp = h >> 5, lane = h & 31;

    const float af  = a[h];
    const float wb  = w[h] * b[h];
    const float l2a = log2f(af);          // relative-accurate (NOT __log2f)
    float p = wb * exp2f((float)(j0 * CHUNK * SUBS) * l2a);

    // block 0: z0 reduce (pure fp32)
    if (j0 == 0) {
        const float aT  = exp2f((float)TLEN * l2a);
        const float geo = (1.0f - aT) / (1.0f - af);
        float term = w[h] * c[h] * geo;
        #pragma unroll
        for (int off = 16; off; off >>= 1)
            term += __shfl_down_sync(0xffffffffu, term, off);
        if (lane == 0) zp[warp] = term;
    }

    #pragma unroll
    for (int sub = 0; sub < SUBS; sub++) {
        #pragma unroll
        for (int i = 0; i < CHUNK; i++) { part[i][h] = p; p *= af; }
        __syncthreads();

        // warp i reduces h-dimension for t-offset i of this sub-chunk
        float s = 0.0f;
        #pragma unroll
        for (int k = 0; k < HDIM / 32; k++) s += part[warp][lane + 32 * k];
        #pragma unroll
        for (int off = 16; off; off >>= 1) s += __shfl_down_sync(0xffffffffu, s, off);
        if (lane == 0)
            g_K[TLEN - 1 - (j0 * CHUNK * SUBS + sub * CHUNK + warp)] = s;
        __syncthreads();
    }

    // block 0: finish z0 and init out[row] = z0 + e (before launch_dependents!)
    if (j0 == 0) {
        if (h == 0) {
            float sz = 0.0f;
            #pragma unroll
            for (int i = 0; i < 16; i++) sz += zp[i];
            s_z0 = sz + e[0];
        }
        __syncthreads();
        if (h < BATCH) out[h] = s_z0;
    }

    // All g_K / out stores issued -> release the dependent grid.
    asm volatile("griddepcontrol.launch_dependents;");
}

// Kernel 2 (PDL secondary): 256 blocks x 256 threads; (row, seg) per block.
// Each block dots a contiguous 4 KB x-segment with the matching K-segment and
// RED-adds its partial into out[row] (initialized by build_K).
__global__ __launch_bounds__(256) void dot_kernel(
    const float* __restrict__ x, float* __restrict__ out)
{
    const int row = blockIdx.x >> 2;
    const int seg = blockIdx.x & (DSEG - 1);
    const int tid = threadIdx.x;
    const int t0  = seg * (TLEN / DSEG);          // 1024

    // prefetch x before the PDL wait (overlaps primary grid)
    const float4 xv = ((const float4*)(x + (size_t)row * TLEN + t0))[tid];

    asm volatile("griddepcontrol.wait;" ::: "memory");

    const float4 kv = __ldcg(&((const float4*)(g_K + t0))[tid]);

    float s = xv.x * kv.x + xv.y * kv.y + xv.z * kv.z + xv.w * kv.w;
    #pragma unroll
    for (int off = 16; off; off >>= 1) s += __shfl_down_sync(0xffffffffu, s, off);

    __shared__ float sp[8];
    const int warp = tid >> 5, lane = tid & 31;
    if (lane == 0) sp[warp] = s;
    __syncthreads();
    if (tid == 0) {
        float t = 0.0f;
        #pragma unroll
        for (int i = 0; i < 8; i++) t += sp[i];
        atomicAdd(&out[row], t);   // REDG, no return
    }
}

extern "C" void kernel_launch(void* const* d_in, const int* in_sizes, int n_in,
                              void* d_out, int out_size)
{
    const float* x = (const float*)d_in[0];   // [B, T]
    const float* a = (const float*)d_in[1];   // [H]
    const float* b = (const float*)d_in[2];   // [H]
    const float* c = (const float*)d_in[3];   // [H]
    const float* w = (const float*)d_in[4];   // [H]
    const float* e = (const float*)d_in[5];   // [1]
    float* out = (float*)d_out;               // [B]

    build_K_kernel<<<NBLK, HDIM>>>(a, b, c, w, e, out);

    // dot as programmatic dependent of build_K (PDL edge; graph-capturable)
    cudaLaunchAttribute attrs[1];
    attrs[0].id = cudaLaunchAttributeProgrammaticStreamSerialization;
    attrs[0].val.programmaticStreamSerializationAllowed = 1;
    cudaLaunchConfig_t cfg = {};
    cfg.gridDim  = dim3(BATCH * DSEG);
    cfg.blockDim = dim3(256);
    cfg.dynamicSmemBytes = 0;
    cfg.stream = 0;
    cfg.attrs = attrs;
    cfg.numAttrs = 1;
    cudaLaunchKernelEx(&cfg, dot_kernel, x, out);
}

// round 8
// speedup vs baseline: 2.0358x; 2.0358x over previous
#include <cuda_runtime.h>
#include <math.h>

// z[b] = sum_t x[b,t]*K[t] + z0 + e
// K[t] = sum_h w_h*b_h*a_h^(T-1-t),  z0 = sum_h w_h*c_h*(1-a_h^T)/(1-a_h)
#define TLEN 4096
#define HDIM 512
#define BATCH 64
#define CHUNK 16
#define NCHUNK (TLEN / CHUNK)   // 256 blocks

// Scratch (__device__ globals; zero-initialized at load; no allocations)
__device__ __align__(16) float g_K[TLEN];
__device__ float g_z0;
__device__ int   g_done;    // producer completion count (reset by consumers)
__device__ int   g_cdone;   // consumer completion ticket

// Kernel 1 (primary): identical compute to the proven R6 version, but opts the
// dependent grid in IMMEDIATELY (scheduling only); data readiness is signaled
// via g_done after a gpu-scope fence.
__global__ __launch_bounds__(HDIM) void build_K_kernel(
    const float* __restrict__ a, const float* __restrict__ b,
    const float* __restrict__ c, const float* __restrict__ w)
{
    // let dot's CTAs roll out + load x while we compute
    asm volatile("griddepcontrol.launch_dependents;");

    __shared__ float part[CHUNK][HDIM];   // 32 KB
    __shared__ float zp[16];
    const int h = threadIdx.x;
    const int j = blockIdx.x;             // exponents s in [16j, 16j+16)
    const int warp = h >> 5, lane = h & 31;

    const float af  = a[h];
    const float wb  = w[h] * b[h];
    const float l2a = log2f(af);          // relative-accurate (NOT __log2f)
    float p = wb * exp2f((float)(j * CHUNK) * l2a);

    #pragma unroll
    for (int i = 0; i < CHUNK; i++) { part[i][h] = p; p *= af; }

    if (j == 0) {                          // z0 = sum_h w*c*(1-a^T)/(1-a)
        const float aT  = exp2f((float)TLEN * l2a);
        const float geo = (1.0f - aT) / (1.0f - af);
        float term = w[h] * c[h] * geo;
        #pragma unroll
        for (int off = 16; off; off >>= 1)
            term += __shfl_down_sync(0xffffffffu, term, off);
        if (lane == 0) zp[warp] = term;
    }
    __syncthreads();

    // warp i reduces the h-dimension for t-offset i
    float s = 0.0f;
    #pragma unroll
    for (int k = 0; k < HDIM / 32; k++) s += part[warp][lane + 32 * k];
    #pragma unroll
    for (int off = 16; off; off >>= 1) s += __shfl_down_sync(0xffffffffu, s, off);
    if (lane == 0) g_K[TLEN - 1 - (j * CHUNK + warp)] = s;

    if (j == 0 && h == 0) {
        float sz = 0.0f;
        #pragma unroll
        for (int i = 0; i < 16; i++) sz += zp[i];
        g_z0 = sz;
    }

    // release: make this CTA's g_K/g_z0 stores L2-visible, then count in
    __threadfence();
    __syncthreads();
    if (h == 0) atomicAdd(&g_done, 1);
}

// Kernel 2 (PDL secondary, launches at build_K start): one block per row,
// 512 threads, 8 x-elements per thread. x loads issued BEFORE the spin.
__global__ __launch_bounds__(HDIM) void dot_kernel(
    const float* __restrict__ x, const float* __restrict__ e,
    float* __restrict__ out)
{
    const int row = blockIdx.x;
    const int tid = threadIdx.x;

    asm volatile("griddepcontrol.wait;" ::: "memory");  // scheduling gate only

    // prefetch x (1 MB grid-wide in flight) + e while build_K computes
    const float4* xr = (const float4*)(x + (size_t)row * TLEN);
    const float4 v0 = xr[tid];
    const float4 v1 = xr[tid + HDIM];
    const float ev = e[0];

    // data-readiness spin: producers counted in after gpu-scope fence
    __shared__ int s_ready;
    if (tid == 0) {
        while (*((volatile int*)&g_done) < NCHUNK) { }
        s_ready = 1;
    }
    __syncthreads();
    (void)s_ready;

    const float4 k0 = __ldcg(&((const float4*)g_K)[tid]);
    const float4 k1 = __ldcg(&((const float4*)g_K)[tid + HDIM]);

    float s = v0.x * k0.x + v0.y * k0.y + v0.z * k0.z + v0.w * k0.w
            + v1.x * k1.x + v1.y * k1.y + v1.z * k1.z + v1.w * k1.w;
    #pragma unroll
    for (int off = 16; off; off >>= 1) s += __shfl_down_sync(0xffffffffu, s, off);

    __shared__ float sp[16];
    const int warp = tid >> 5, lane = tid & 31;
    if (lane == 0) sp[warp] = s;
    __syncthreads();

    if (warp == 0) {
        float t = (lane < 16) ? sp[lane] : 0.0f;
        #pragma unroll
        for (int off = 8; off; off >>= 1) t += __shfl_down_sync(0xffffffffu, t, off);
        if (lane == 0) out[row] = t + __ldcg(&g_z0) + ev;
    }

    // last consumer block resets the flags for the next graph replay
    __syncthreads();
    if (tid == 0) {
        int r = atomicAdd(&g_cdone, 1);
        if (r == BATCH - 1) {
            g_done  = 0;
            g_cdone = 0;
            __threadfence();
        }
    }
}

extern "C" void kernel_launch(void* const* d_in, const int* in_sizes, int n_in,
                              void* d_out, int out_size)
{
    const float* x = (const float*)d_in[0];   // [B, T]
    const float* a = (const float*)d_in[1];   // [H]
    const float* b = (const float*)d_in[2];   // [H]
    const float* c = (const float*)d_in[3];   // [H]
    const float* w = (const float*)d_in[4];   // [H]
    const float* e = (const float*)d_in[5];   // [1]
    float* out = (float*)d_out;               // [B]

    build_K_kernel<<<NCHUNK, HDIM>>>(a, b, c, w);

    // dot as programmatic dependent (launches at build_K start)
    cudaLaunchAttribute attrs[1];
    attrs[0].id = cudaLaunchAttributeProgrammaticStreamSerialization;
    attrs[0].val.programmaticStreamSerializationAllowed = 1;
    cudaLaunchConfig_t cfg = {};
    cfg.gridDim  = dim3(BATCH);
    cfg.blockDim = dim3(HDIM);
    cfg.dynamicSmemBytes = 0;
    cfg.stream = 0;
    cfg.attrs = attrs;
    cfg.numAttrs = 1;
    cudaLaunchKernelEx(&cfg, dot_kernel, x, e, out);
}